// round 1
// baseline (speedup 1.0000x reference)
#include <cuda_runtime.h>
#include <math.h>

#define TTOK 2048
#define HDIM 2048
#define IDIM 1024
#define ENUM 64
#define KTOP 8

#define BM 64
#define BN 64
#define BK 16

// Scratch (static device globals; no dynamic allocation allowed)
__device__ int   g_cnt[ENUM];
__device__ int   g_off[ENUM];
__device__ int   g_tok[ENUM * TTOK];
__device__ float g_wt[ENUM * TTOK];
__device__ float g_h[(size_t)TTOK * KTOP * IDIM];   // 16384 x 1024 = 64 MB

// ---------------------------------------------------------------------------
// K0: zero the main output region (atomic-accumulated later) + reset counters
// ---------------------------------------------------------------------------
__global__ void zero_kernel(float* __restrict__ out) {
    size_t idx = (size_t)blockIdx.x * blockDim.x + threadIdx.x;
    size_t n4 = (size_t)TTOK * HDIM / 4;
    float4 z = make_float4(0.f, 0.f, 0.f, 0.f);
    for (size_t i = idx; i < n4; i += (size_t)gridDim.x * blockDim.x)
        reinterpret_cast<float4*>(out)[i] = z;
    if (blockIdx.x == 0 && threadIdx.x < ENUM) g_cnt[threadIdx.x] = 0;
}

// ---------------------------------------------------------------------------
// K1: router — logits, softmax, top-8, append (token, weight) to expert lists
// ---------------------------------------------------------------------------
__global__ void router_kernel(const float* __restrict__ x,
                              const float* __restrict__ gw,
                              float* __restrict__ out) {
    int t = blockIdx.x;
    __shared__ float xs[HDIM];
    __shared__ float logits[ENUM];
    __shared__ float probs[ENUM];

    const float* xr = x + (size_t)t * HDIM;
    for (int i = threadIdx.x; i < HDIM; i += blockDim.x) xs[i] = xr[i];
    __syncthreads();

    // 4 partial sums per expert (256 threads = 64 experts x 4 parts)
    int e = threadIdx.x >> 2;
    int part = threadIdx.x & 3;
    float s = 0.f;
    int k0 = part * (HDIM / 4);
    for (int k = k0; k < k0 + HDIM / 4; k++)
        s += xs[k] * gw[(size_t)k * ENUM + e];
    s += __shfl_down_sync(0xffffffffu, s, 2);
    s += __shfl_down_sync(0xffffffffu, s, 1);
    if (part == 0) logits[e] = s;
    __syncthreads();

    if (threadIdx.x < ENUM)
        out[(size_t)TTOK * HDIM + (size_t)t * ENUM + threadIdx.x] = logits[threadIdx.x];

    if (threadIdx.x == 0) {
        float m = -1e30f;
        for (int i = 0; i < ENUM; i++) m = fmaxf(m, logits[i]);
        float sum = 0.f;
        for (int i = 0; i < ENUM; i++) { probs[i] = expf(logits[i] - m); sum += probs[i]; }
        float inv = 1.f / sum;
        for (int k = 0; k < KTOP; k++) {
            int best = 0; float bv = -1.f;
            for (int i = 0; i < ENUM; i++)
                if (probs[i] > bv) { bv = probs[i]; best = i; }
            probs[best] = -2.f;
            int pos = atomicAdd(&g_cnt[best], 1);
            g_tok[best * TTOK + pos] = t;
            g_wt[best * TTOK + pos]  = bv * inv;
        }
    }
}

// ---------------------------------------------------------------------------
// K2: exclusive prefix sum over expert counts (trivial, 64 entries)
// ---------------------------------------------------------------------------
__global__ void scan_kernel() {
    if (threadIdx.x == 0) {
        int acc = 0;
        for (int e = 0; e < ENUM; e++) { g_off[e] = acc; acc += g_cnt[e]; }
    }
}

// ---------------------------------------------------------------------------
// K3: per-expert gate+up GEMM (gathered rows) + fused SiLU*up -> g_h
//   M = cnt[e] (<=2048), N = IDIM, K = HDIM
// ---------------------------------------------------------------------------
__global__ __launch_bounds__(256)
void gateup_kernel(const float* __restrict__ x,
                   const float* __restrict__ wgp,
                   const float* __restrict__ wup) {
    int e = blockIdx.z;
    int cnt = g_cnt[e];
    int m0 = blockIdx.y * BM;
    if (m0 >= cnt) return;
    int n0 = blockIdx.x * BN;

    const float* Wg = wgp + (size_t)e * HDIM * IDIM;
    const float* Wu = wup + (size_t)e * HDIM * IDIM;

    __shared__ float As[BK][BM];
    __shared__ float Bg[BK][BN];
    __shared__ float Bu[BK][BN];

    int tid = threadIdx.x;
    int tx = tid & 15, ty = tid >> 4;

    // A-tile load mapping: 64 rows x 16 cols, one float4 per thread
    int lr = tid >> 2;
    int lc = (tid & 3) * 4;
    int mrow = min(m0 + lr, cnt - 1);
    int tok = g_tok[e * TTOK + mrow];
    const float* arow = x + (size_t)tok * HDIM;

    // B-tile load mapping: 16 rows x 64 cols, one float4 per thread
    int br = tid >> 4;
    int bc = (tid & 15) * 4;

    float accg[4][4] = {}, accu[4][4] = {};

    for (int k0 = 0; k0 < HDIM; k0 += BK) {
        float4 av = *reinterpret_cast<const float4*>(arow + k0 + lc);
        As[lc + 0][lr] = av.x;
        As[lc + 1][lr] = av.y;
        As[lc + 2][lr] = av.z;
        As[lc + 3][lr] = av.w;
        *reinterpret_cast<float4*>(&Bg[br][bc]) =
            *reinterpret_cast<const float4*>(Wg + (size_t)(k0 + br) * IDIM + n0 + bc);
        *reinterpret_cast<float4*>(&Bu[br][bc]) =
            *reinterpret_cast<const float4*>(Wu + (size_t)(k0 + br) * IDIM + n0 + bc);
        __syncthreads();
#pragma unroll
        for (int kk = 0; kk < BK; kk++) {
            float4 a  = *reinterpret_cast<const float4*>(&As[kk][ty * 4]);
            float4 bg = *reinterpret_cast<const float4*>(&Bg[kk][tx * 4]);
            float4 bu = *reinterpret_cast<const float4*>(&Bu[kk][tx * 4]);
            float aa[4] = {a.x, a.y, a.z, a.w};
            float gg[4] = {bg.x, bg.y, bg.z, bg.w};
            float uu[4] = {bu.x, bu.y, bu.z, bu.w};
#pragma unroll
            for (int i = 0; i < 4; i++)
#pragma unroll
                for (int j = 0; j < 4; j++) {
                    accg[i][j] = fmaf(aa[i], gg[j], accg[i][j]);
                    accu[i][j] = fmaf(aa[i], uu[j], accu[i][j]);
                }
        }
        __syncthreads();
    }

#pragma unroll
    for (int i = 0; i < 4; i++) {
        int m = m0 + ty * 4 + i;
        if (m >= cnt) continue;
        float* hrow = g_h + (size_t)(g_off[e] + m) * IDIM + n0 + tx * 4;
#pragma unroll
        for (int j = 0; j < 4; j++) {
            float g = accg[i][j];
            float sg = g / (1.f + expf(-g));   // SiLU
            hrow[j] = sg * accu[i][j];
        }
    }
}

// ---------------------------------------------------------------------------
// K4: per-expert down GEMM + weighted atomic scatter into output rows
//   M = cnt[e], N = HDIM, K = IDIM
// ---------------------------------------------------------------------------
__global__ __launch_bounds__(256)
void down_kernel(const float* __restrict__ wdp,
                 float* __restrict__ out) {
    int e = blockIdx.z;
    int cnt = g_cnt[e];
    int m0 = blockIdx.y * BM;
    if (m0 >= cnt) return;
    int n0 = blockIdx.x * BN;

    const float* Wd = wdp + (size_t)e * IDIM * HDIM;

    __shared__ float As[BK][BM];
    __shared__ float Bs[BK][BN];

    int tid = threadIdx.x;
    int tx = tid & 15, ty = tid >> 4;
    int lr = tid >> 2;
    int lc = (tid & 3) * 4;
    int mrow = min(m0 + lr, cnt - 1);
    const float* arow = g_h + (size_t)(g_off[e] + mrow) * IDIM;
    int br = tid >> 4;
    int bc = (tid & 15) * 4;

    float acc[4][4] = {};

    for (int k0 = 0; k0 < IDIM; k0 += BK) {
        float4 av = *reinterpret_cast<const float4*>(arow + k0 + lc);
        As[lc + 0][lr] = av.x;
        As[lc + 1][lr] = av.y;
        As[lc + 2][lr] = av.z;
        As[lc + 3][lr] = av.w;
        *reinterpret_cast<float4*>(&Bs[br][bc]) =
            *reinterpret_cast<const float4*>(Wd + (size_t)(k0 + br) * HDIM + n0 + bc);
        __syncthreads();
#pragma unroll
        for (int kk = 0; kk < BK; kk++) {
            float4 a = *reinterpret_cast<const float4*>(&As[kk][ty * 4]);
            float4 b = *reinterpret_cast<const float4*>(&Bs[kk][tx * 4]);
            float aa[4] = {a.x, a.y, a.z, a.w};
            float bb[4] = {b.x, b.y, b.z, b.w};
#pragma unroll
            for (int i = 0; i < 4; i++)
#pragma unroll
                for (int j = 0; j < 4; j++)
                    acc[i][j] = fmaf(aa[i], bb[j], acc[i][j]);
        }
        __syncthreads();
    }

#pragma unroll
    for (int i = 0; i < 4; i++) {
        int m = m0 + ty * 4 + i;
        if (m >= cnt) continue;
        int tok = g_tok[e * TTOK + m];
        float w = g_wt[e * TTOK + m];
        float* orow = out + (size_t)tok * HDIM + n0 + tx * 4;
#pragma unroll
        for (int j = 0; j < 4; j++)
            atomicAdd(&orow[j], w * acc[i][j]);
    }
}

// ---------------------------------------------------------------------------
extern "C" void kernel_launch(void* const* d_in, const int* in_sizes, int n_in,
                              void* d_out, int out_size) {
    const float* x  = (const float*)d_in[0];   // hidden_states [2,1024,2048]
    const float* gw = (const float*)d_in[1];   // gate_w [2048,64]
    const float* wg = (const float*)d_in[2];   // w_gate_proj [64,2048,1024]
    const float* wu = (const float*)d_in[3];   // w_up_proj   [64,2048,1024]
    const float* wd = (const float*)d_in[4];   // w_down_proj [64,1024,2048]
    float* out = (float*)d_out;                // [final | router_logits]

    zero_kernel<<<1024, 256>>>(out);
    router_kernel<<<TTOK, 256>>>(x, gw, out);
    scan_kernel<<<1, 32>>>();
    dim3 g3(IDIM / BN, TTOK / BM, ENUM);       // 16 x 32 x 64
    gateup_kernel<<<g3, 256>>>(x, wg, wu);
    dim3 g4(HDIM / BN, TTOK / BM, ENUM);       // 32 x 32 x 64
    down_kernel<<<g4, 256>>>(wd, out);
}

// round 4
// speedup vs baseline: 1.5036x; 1.5036x over previous
#include <cuda_runtime.h>
#include <cuda_bf16.h>
#include <math.h>
#include <stdint.h>

#define TTOK 2048
#define HDIM 2048
#define IDIM 1024
#define ENUM 64
#define KTOP 8

// Scratch (static device globals; no dynamic allocation allowed)
__device__ int   g_cnt[ENUM];
__device__ int   g_off[ENUM];
__device__ int   g_tok[ENUM * TTOK];
__device__ float g_wt[ENUM * TTOK];
__device__ float g_h[(size_t)TTOK * KTOP * IDIM];   // 16384 x 1024 = 64 MB

// ---------------------------------------------------------------------------
// helpers
// ---------------------------------------------------------------------------
__device__ __forceinline__ uint32_t cvsm(const void* p) {
    return (uint32_t)__cvta_generic_to_shared(p);
}
__device__ __forceinline__ void ldsm4(uint32_t& r0, uint32_t& r1, uint32_t& r2, uint32_t& r3, uint32_t a) {
    asm volatile("ldmatrix.sync.aligned.m8n8.x4.shared.b16 {%0,%1,%2,%3},[%4];"
                 : "=r"(r0), "=r"(r1), "=r"(r2), "=r"(r3) : "r"(a));
}
__device__ __forceinline__ void ldsm4t(uint32_t& r0, uint32_t& r1, uint32_t& r2, uint32_t& r3, uint32_t a) {
    asm volatile("ldmatrix.sync.aligned.m8n8.x4.trans.shared.b16 {%0,%1,%2,%3},[%4];"
                 : "=r"(r0), "=r"(r1), "=r"(r2), "=r"(r3) : "r"(a));
}
__device__ __forceinline__ void mma16816(float* c, const uint32_t* a, const uint32_t* b) {
    asm volatile("mma.sync.aligned.m16n8k16.row.col.f32.bf16.bf16.f32 "
                 "{%0,%1,%2,%3},{%4,%5,%6,%7},{%8,%9},{%0,%1,%2,%3};"
                 : "+f"(c[0]), "+f"(c[1]), "+f"(c[2]), "+f"(c[3])
                 : "r"(a[0]), "r"(a[1]), "r"(a[2]), "r"(a[3]), "r"(b[0]), "r"(b[1]));
}
// split two fp32 into packed bf16 hi and packed bf16 lo (residual)
__device__ __forceinline__ void splitf(float a, float b, uint32_t& hi, uint32_t& lo) {
    __nv_bfloat16 ah = __float2bfloat16(a);
    __nv_bfloat16 bh = __float2bfloat16(b);
    __nv_bfloat16 al = __float2bfloat16(a - __bfloat162float(ah));
    __nv_bfloat16 bl = __float2bfloat16(b - __bfloat162float(bh));
    hi = ((uint32_t)__bfloat16_as_ushort(bh) << 16) | (uint32_t)__bfloat16_as_ushort(ah);
    lo = ((uint32_t)__bfloat16_as_ushort(bl) << 16) | (uint32_t)__bfloat16_as_ushort(al);
}

// ---------------------------------------------------------------------------
// K0: zero output accumulation region + reset counters
// ---------------------------------------------------------------------------
__global__ void zero_kernel(float* __restrict__ out) {
    size_t idx = (size_t)blockIdx.x * blockDim.x + threadIdx.x;
    size_t n4 = (size_t)TTOK * HDIM / 4;
    float4 z = make_float4(0.f, 0.f, 0.f, 0.f);
    for (size_t i = idx; i < n4; i += (size_t)gridDim.x * blockDim.x)
        reinterpret_cast<float4*>(out)[i] = z;
    if (blockIdx.x == 0 && threadIdx.x < ENUM) g_cnt[threadIdx.x] = 0;
}

// ---------------------------------------------------------------------------
// K1: router — logits, softmax, top-8, append (token, weight) to expert lists
// ---------------------------------------------------------------------------
__global__ void router_kernel(const float* __restrict__ x,
                              const float* __restrict__ gw,
                              float* __restrict__ out) {
    int t = blockIdx.x;
    __shared__ float xs[HDIM];
    __shared__ float logits[ENUM];
    __shared__ float probs[ENUM];

    const float* xr = x + (size_t)t * HDIM;
    for (int i = threadIdx.x; i < HDIM; i += blockDim.x) xs[i] = xr[i];
    __syncthreads();

    int e = threadIdx.x >> 2;
    int part = threadIdx.x & 3;
    float s = 0.f;
    int k0 = part * (HDIM / 4);
    for (int k = k0; k < k0 + HDIM / 4; k++)
        s += xs[k] * gw[(size_t)k * ENUM + e];
    s += __shfl_down_sync(0xffffffffu, s, 2);
    s += __shfl_down_sync(0xffffffffu, s, 1);
    if (part == 0) logits[e] = s;
    __syncthreads();

    if (threadIdx.x < ENUM)
        out[(size_t)TTOK * HDIM + (size_t)t * ENUM + threadIdx.x] = logits[threadIdx.x];

    if (threadIdx.x == 0) {
        float m = -1e30f;
        for (int i = 0; i < ENUM; i++) m = fmaxf(m, logits[i]);
        float sum = 0.f;
        for (int i = 0; i < ENUM; i++) { probs[i] = expf(logits[i] - m); sum += probs[i]; }
        float inv = 1.f / sum;
        for (int k = 0; k < KTOP; k++) {
            int best = 0; float bv = -1.f;
            for (int i = 0; i < ENUM; i++)
                if (probs[i] > bv) { bv = probs[i]; best = i; }
            probs[best] = -2.f;
            int pos = atomicAdd(&g_cnt[best], 1);
            g_tok[best * TTOK + pos] = t;
            g_wt[best * TTOK + pos]  = bv * inv;
        }
    }
}

// ---------------------------------------------------------------------------
// K2: exclusive prefix sum over expert counts
// ---------------------------------------------------------------------------
__global__ void scan_kernel() {
    if (threadIdx.x == 0) {
        int acc = 0;
        for (int e = 0; e < ENUM; e++) { g_off[e] = acc; acc += g_cnt[e]; }
    }
}

// ---------------------------------------------------------------------------
// K3: gateup via bf16x3 tensor-core mma. BM=128, BN=64 per matrix, BK=16.
// ---------------------------------------------------------------------------
#define GU_ITERS (HDIM / 16)

__global__ __launch_bounds__(256, 1)
void gateup_mma(const float* __restrict__ x,
                const float* __restrict__ wgp,
                const float* __restrict__ wup) {
    int e = blockIdx.z;
    int cnt = g_cnt[e];
    int mblk = blockIdx.y * 128;
    if (mblk >= cnt) return;
    int nblk = blockIdx.x * 64;

    __shared__ unsigned short Ah[2][128][24], Al[2][128][24];
    __shared__ unsigned short Bh[2][2][16][72], Bl[2][2][16][72]; // [stage][mat][k][n]

    const int tid = threadIdx.x;
    const int lane = tid & 31, warp = tid >> 5;
    const int wm = warp >> 1, wn = warp & 1;

    // A tile load mapping: 128m x 16k, 8 fp32/thread
    const int am = tid >> 1;
    const int ak = (tid & 1) * 8;
    int mrow = min(mblk + am, cnt - 1);
    const float* arow = x + (size_t)g_tok[e * TTOK + mrow] * HDIM + ak;

    // B tile load mapping: 64n x 16k per matrix, half the block each
    const int bmat = tid >> 7;
    const int bk = (tid & 127) >> 3;
    const int bn = (tid & 7) * 8;
    const float* Wsel = (bmat ? wup : wgp) + (size_t)e * HDIM * IDIM;
    const float* brow = Wsel + (size_t)bk * IDIM + nblk + bn;

    float4 pa0, pa1, pb0, pb1;
    pa0 = *(const float4*)(arow);
    pa1 = *(const float4*)(arow + 4);
    pb0 = *(const float4*)(brow);
    pb1 = *(const float4*)(brow + 4);

    float cg[2][4][4] = {}, cu[2][4][4] = {};

    int s = 0;
    // initial store of tile 0
    {
        uint32_t h0, l0, h1, l1, h2, l2, h3, l3;
        splitf(pa0.x, pa0.y, h0, l0); splitf(pa0.z, pa0.w, h1, l1);
        splitf(pa1.x, pa1.y, h2, l2); splitf(pa1.z, pa1.w, h3, l3);
        *(uint4*)&Ah[0][am][ak] = make_uint4(h0, h1, h2, h3);
        *(uint4*)&Al[0][am][ak] = make_uint4(l0, l1, l2, l3);
        splitf(pb0.x, pb0.y, h0, l0); splitf(pb0.z, pb0.w, h1, l1);
        splitf(pb1.x, pb1.y, h2, l2); splitf(pb1.z, pb1.w, h3, l3);
        *(uint4*)&Bh[0][bmat][bk][bn] = make_uint4(h0, h1, h2, h3);
        *(uint4*)&Bl[0][bmat][bk][bn] = make_uint4(l0, l1, l2, l3);
    }
    __syncthreads();

    for (int it = 0; it < GU_ITERS; ++it) {
        if (it + 1 < GU_ITERS) {
            const float* a2 = arow + (it + 1) * 16;
            pa0 = *(const float4*)a2; pa1 = *(const float4*)(a2 + 4);
            const float* b2 = brow + (size_t)(it + 1) * 16 * IDIM;
            pb0 = *(const float4*)b2; pb1 = *(const float4*)(b2 + 4);
        }

        // fragments
        uint32_t aH[2][4], aL[2][4];
#pragma unroll
        for (int mf = 0; mf < 2; mf++) {
            uint32_t ad = cvsm(&Ah[s][wm * 32 + mf * 16 + (lane & 15)][(lane >> 4) * 8]);
            ldsm4(aH[mf][0], aH[mf][1], aH[mf][2], aH[mf][3], ad);
            uint32_t ad2 = cvsm(&Al[s][wm * 32 + mf * 16 + (lane & 15)][(lane >> 4) * 8]);
            ldsm4(aL[mf][0], aL[mf][1], aL[mf][2], aL[mf][3], ad2);
        }
        uint32_t bgH[4][2], bgL[4][2], buH[4][2], buL[4][2];
#pragma unroll
        for (int p = 0; p < 2; p++) {
            int col = wn * 32 + p * 16 + (lane >> 4) * 8;
            int row = lane & 15;
            uint32_t d0 = cvsm(&Bh[s][0][row][col]);
            ldsm4t(bgH[2 * p][0], bgH[2 * p][1], bgH[2 * p + 1][0], bgH[2 * p + 1][1], d0);
            uint32_t d1 = cvsm(&Bl[s][0][row][col]);
            ldsm4t(bgL[2 * p][0], bgL[2 * p][1], bgL[2 * p + 1][0], bgL[2 * p + 1][1], d1);
            uint32_t d2 = cvsm(&Bh[s][1][row][col]);
            ldsm4t(buH[2 * p][0], buH[2 * p][1], buH[2 * p + 1][0], buH[2 * p + 1][1], d2);
            uint32_t d3 = cvsm(&Bl[s][1][row][col]);
            ldsm4t(buL[2 * p][0], buL[2 * p][1], buL[2 * p + 1][0], buL[2 * p + 1][1], d3);
        }
#pragma unroll
        for (int mf = 0; mf < 2; mf++)
#pragma unroll
            for (int nf = 0; nf < 4; nf++) {
                mma16816(cg[mf][nf], aH[mf], bgH[nf]);
                mma16816(cg[mf][nf], aH[mf], bgL[nf]);
                mma16816(cg[mf][nf], aL[mf], bgH[nf]);
                mma16816(cu[mf][nf], aH[mf], buH[nf]);
                mma16816(cu[mf][nf], aH[mf], buL[nf]);
                mma16816(cu[mf][nf], aL[mf], buH[nf]);
            }

        if (it + 1 < GU_ITERS) {
            uint32_t h0, l0, h1, l1, h2, l2, h3, l3;
            splitf(pa0.x, pa0.y, h0, l0); splitf(pa0.z, pa0.w, h1, l1);
            splitf(pa1.x, pa1.y, h2, l2); splitf(pa1.z, pa1.w, h3, l3);
            *(uint4*)&Ah[s ^ 1][am][ak] = make_uint4(h0, h1, h2, h3);
            *(uint4*)&Al[s ^ 1][am][ak] = make_uint4(l0, l1, l2, l3);
            splitf(pb0.x, pb0.y, h0, l0); splitf(pb0.z, pb0.w, h1, l1);
            splitf(pb1.x, pb1.y, h2, l2); splitf(pb1.z, pb1.w, h3, l3);
            *(uint4*)&Bh[s ^ 1][bmat][bk][bn] = make_uint4(h0, h1, h2, h3);
            *(uint4*)&Bl[s ^ 1][bmat][bk][bn] = make_uint4(l0, l1, l2, l3);
        }
        __syncthreads();
        s ^= 1;
    }

    // epilogue: SiLU(gate)*up -> g_h
    int goff = g_off[e];
    int gr = lane >> 2, cc = (lane & 3) * 2;
#pragma unroll
    for (int mf = 0; mf < 2; mf++)
#pragma unroll
        for (int nf = 0; nf < 4; nf++) {
            int nab = nblk + wn * 32 + nf * 8 + cc;
#pragma unroll
            for (int half = 0; half < 2; half++) {
                int m = mblk + wm * 32 + mf * 16 + gr + half * 8;
                if (m < cnt) {
                    float g0 = cg[mf][nf][half * 2], g1 = cg[mf][nf][half * 2 + 1];
                    float u0 = cu[mf][nf][half * 2], u1 = cu[mf][nf][half * 2 + 1];
                    float h0 = g0 / (1.f + expf(-g0)) * u0;
                    float h1 = g1 / (1.f + expf(-g1)) * u1;
                    *(float2*)&g_h[(size_t)(goff + m) * IDIM + nab] = make_float2(h0, h1);
                }
            }
        }
}

// ---------------------------------------------------------------------------
// K4: down via bf16x3 mma + weighted atomic scatter. BM=128, BN=128, BK=16.
// ---------------------------------------------------------------------------
#define DN_ITERS (IDIM / 16)

__global__ __launch_bounds__(256, 1)
void down_mma(const float* __restrict__ wdp,
              float* __restrict__ out) {
    int e = blockIdx.z;
    int cnt = g_cnt[e];
    int mblk = blockIdx.y * 128;
    if (mblk >= cnt) return;
    int nblk = blockIdx.x * 128;

    __shared__ unsigned short Ah[2][128][24], Al[2][128][24];
    __shared__ unsigned short Bh[2][16][136], Bl[2][16][136];  // [stage][k][n]

    const int tid = threadIdx.x;
    const int lane = tid & 31, warp = tid >> 5;
    const int wm = warp >> 2, wn = warp & 3;

    const int am = tid >> 1;
    const int ak = (tid & 1) * 8;
    int goff = g_off[e];
    int mrow = min(mblk + am, cnt - 1);
    const float* arow = g_h + (size_t)(goff + mrow) * IDIM + ak;

    const int bk = tid >> 4;
    const int bn = (tid & 15) * 8;
    const float* brow = wdp + (size_t)e * IDIM * HDIM + (size_t)bk * HDIM + nblk + bn;

    float4 pa0, pa1, pb0, pb1;
    pa0 = *(const float4*)(arow);
    pa1 = *(const float4*)(arow + 4);
    pb0 = *(const float4*)(brow);
    pb1 = *(const float4*)(brow + 4);

    float cacc[4][4][4] = {};

    int s = 0;
    {
        uint32_t h0, l0, h1, l1, h2, l2, h3, l3;
        splitf(pa0.x, pa0.y, h0, l0); splitf(pa0.z, pa0.w, h1, l1);
        splitf(pa1.x, pa1.y, h2, l2); splitf(pa1.z, pa1.w, h3, l3);
        *(uint4*)&Ah[0][am][ak] = make_uint4(h0, h1, h2, h3);
        *(uint4*)&Al[0][am][ak] = make_uint4(l0, l1, l2, l3);
        splitf(pb0.x, pb0.y, h0, l0); splitf(pb0.z, pb0.w, h1, l1);
        splitf(pb1.x, pb1.y, h2, l2); splitf(pb1.z, pb1.w, h3, l3);
        *(uint4*)&Bh[0][bk][bn] = make_uint4(h0, h1, h2, h3);
        *(uint4*)&Bl[0][bk][bn] = make_uint4(l0, l1, l2, l3);
    }
    __syncthreads();

    for (int it = 0; it < DN_ITERS; ++it) {
        if (it + 1 < DN_ITERS) {
            const float* a2 = arow + (it + 1) * 16;
            pa0 = *(const float4*)a2; pa1 = *(const float4*)(a2 + 4);
            const float* b2 = brow + (size_t)(it + 1) * 16 * HDIM;
            pb0 = *(const float4*)b2; pb1 = *(const float4*)(b2 + 4);
        }

        uint32_t aH[4][4], aL[4][4];
#pragma unroll
        for (int mf = 0; mf < 4; mf++) {
            uint32_t ad = cvsm(&Ah[s][wm * 64 + mf * 16 + (lane & 15)][(lane >> 4) * 8]);
            ldsm4(aH[mf][0], aH[mf][1], aH[mf][2], aH[mf][3], ad);
            uint32_t ad2 = cvsm(&Al[s][wm * 64 + mf * 16 + (lane & 15)][(lane >> 4) * 8]);
            ldsm4(aL[mf][0], aL[mf][1], aL[mf][2], aL[mf][3], ad2);
        }
        uint32_t bH[4][2], bL[4][2];
#pragma unroll
        for (int p = 0; p < 2; p++) {
            int col = wn * 32 + p * 16 + (lane >> 4) * 8;
            int row = lane & 15;
            uint32_t d0 = cvsm(&Bh[s][row][col]);
            ldsm4t(bH[2 * p][0], bH[2 * p][1], bH[2 * p + 1][0], bH[2 * p + 1][1], d0);
            uint32_t d1 = cvsm(&Bl[s][row][col]);
            ldsm4t(bL[2 * p][0], bL[2 * p][1], bL[2 * p + 1][0], bL[2 * p + 1][1], d1);
        }
#pragma unroll
        for (int mf = 0; mf < 4; mf++)
#pragma unroll
            for (int nf = 0; nf < 4; nf++) {
                mma16816(cacc[mf][nf], aH[mf], bH[nf]);
                mma16816(cacc[mf][nf], aH[mf], bL[nf]);
                mma16816(cacc[mf][nf], aL[mf], bH[nf]);
            }

        if (it + 1 < DN_ITERS) {
            uint32_t h0, l0, h1, l1, h2, l2, h3, l3;
            splitf(pa0.x, pa0.y, h0, l0); splitf(pa0.z, pa0.w, h1, l1);
            splitf(pa1.x, pa1.y, h2, l2); splitf(pa1.z, pa1.w, h3, l3);
            *(uint4*)&Ah[s ^ 1][am][ak] = make_uint4(h0, h1, h2, h3);
            *(uint4*)&Al[s ^ 1][am][ak] = make_uint4(l0, l1, l2, l3);
            splitf(pb0.x, pb0.y, h0, l0); splitf(pb0.z, pb0.w, h1, l1);
            splitf(pb1.x, pb1.y, h2, l2); splitf(pb1.z, pb1.w, h3, l3);
            *(uint4*)&Bh[s ^ 1][bk][bn] = make_uint4(h0, h1, h2, h3);
            *(uint4*)&Bl[s ^ 1][bk][bn] = make_uint4(l0, l1, l2, l3);
        }
        __syncthreads();
        s ^= 1;
    }

    // epilogue: weighted atomic scatter into out
    int gr = lane >> 2, cc = (lane & 3) * 2;
#pragma unroll
    for (int mf = 0; mf < 4; mf++) {
#pragma unroll
        for (int half = 0; half < 2; half++) {
            int m = mblk + wm * 64 + mf * 16 + gr + half * 8;
            if (m < cnt) {
                int tok = g_tok[e * TTOK + m];
                float w = g_wt[e * TTOK + m];
                float* orow = out + (size_t)tok * HDIM;
#pragma unroll
                for (int nf = 0; nf < 4; nf++) {
                    int nab = nblk + wn * 32 + nf * 8 + cc;
                    atomicAdd(&orow[nab],     w * cacc[mf][nf][half * 2]);
                    atomicAdd(&orow[nab + 1], w * cacc[mf][nf][half * 2 + 1]);
                }
            }
        }
    }
}

// ---------------------------------------------------------------------------
extern "C" void kernel_launch(void* const* d_in, const int* in_sizes, int n_in,
                              void* d_out, int out_size) {
    const float* x  = (const float*)d_in[0];   // hidden_states [2,1024,2048]
    const float* gw = (const float*)d_in[1];   // gate_w [2048,64]
    const float* wg = (const float*)d_in[2];   // w_gate_proj [64,2048,1024]
    const float* wu = (const float*)d_in[3];   // w_up_proj   [64,2048,1024]
    const float* wd = (const float*)d_in[4];   // w_down_proj [64,1024,2048]
    float* out = (float*)d_out;                // [final | router_logits]

    zero_kernel<<<1024, 256>>>(out);
    router_kernel<<<TTOK, 256>>>(x, gw, out);
    scan_kernel<<<1, 32>>>();
    gateup_mma<<<dim3(16, 16, 64), 256>>>(x, wg, wu);
    down_mma<<<dim3(16, 16, 64), 256>>>(wd, out);
}

// round 5
// speedup vs baseline: 1.7670x; 1.1752x over previous
#include <cuda_runtime.h>
#include <cuda_bf16.h>
#include <math.h>
#include <stdint.h>

#define TTOK 2048
#define HDIM 2048
#define IDIM 1024
#define ENUM 64
#define KTOP 8

// Scratch (static device globals; no dynamic allocation allowed)
__device__ int   g_cnt[ENUM];
__device__ int   g_off[ENUM];
__device__ int   g_tok[ENUM * TTOK];
__device__ float g_wt[ENUM * TTOK];
__device__ float g_h[(size_t)TTOK * KTOP * IDIM];   // 16384 x 1024 = 64 MB

// ---------------------------------------------------------------------------
// helpers
// ---------------------------------------------------------------------------
__device__ __forceinline__ uint32_t cvsm(const void* p) {
    return (uint32_t)__cvta_generic_to_shared(p);
}
__device__ __forceinline__ void ldsm4(uint32_t& r0, uint32_t& r1, uint32_t& r2, uint32_t& r3, uint32_t a) {
    asm volatile("ldmatrix.sync.aligned.m8n8.x4.shared.b16 {%0,%1,%2,%3},[%4];"
                 : "=r"(r0), "=r"(r1), "=r"(r2), "=r"(r3) : "r"(a));
}
__device__ __forceinline__ void ldsm4t(uint32_t& r0, uint32_t& r1, uint32_t& r2, uint32_t& r3, uint32_t a) {
    asm volatile("ldmatrix.sync.aligned.m8n8.x4.trans.shared.b16 {%0,%1,%2,%3},[%4];"
                 : "=r"(r0), "=r"(r1), "=r"(r2), "=r"(r3) : "r"(a));
}
__device__ __forceinline__ void mma16816(float* c, const uint32_t* a, const uint32_t* b) {
    asm volatile("mma.sync.aligned.m16n8k16.row.col.f32.bf16.bf16.f32 "
                 "{%0,%1,%2,%3},{%4,%5,%6,%7},{%8,%9},{%0,%1,%2,%3};"
                 : "+f"(c[0]), "+f"(c[1]), "+f"(c[2]), "+f"(c[3])
                 : "r"(a[0]), "r"(a[1]), "r"(a[2]), "r"(a[3]), "r"(b[0]), "r"(b[1]));
}
// split two fp32 into packed bf16 hi and packed bf16 lo (residual)
__device__ __forceinline__ void splitf(float a, float b, uint32_t& hi, uint32_t& lo) {
    __nv_bfloat16 ah = __float2bfloat16(a);
    __nv_bfloat16 bh = __float2bfloat16(b);
    __nv_bfloat16 al = __float2bfloat16(a - __bfloat162float(ah));
    __nv_bfloat16 bl = __float2bfloat16(b - __bfloat162float(bh));
    hi = ((uint32_t)__bfloat16_as_ushort(bh) << 16) | (uint32_t)__bfloat16_as_ushort(ah);
    lo = ((uint32_t)__bfloat16_as_ushort(bl) << 16) | (uint32_t)__bfloat16_as_ushort(al);
}

// ---------------------------------------------------------------------------
// K0: zero output accumulation region + reset counters
// ---------------------------------------------------------------------------
__global__ void zero_kernel(float* __restrict__ out) {
    size_t idx = (size_t)blockIdx.x * blockDim.x + threadIdx.x;
    size_t n4 = (size_t)TTOK * HDIM / 4;
    float4 z = make_float4(0.f, 0.f, 0.f, 0.f);
    for (size_t i = idx; i < n4; i += (size_t)gridDim.x * blockDim.x)
        reinterpret_cast<float4*>(out)[i] = z;
    if (blockIdx.x == 0 && threadIdx.x < ENUM) g_cnt[threadIdx.x] = 0;
}

// ---------------------------------------------------------------------------
// K1: router — logits, softmax, top-8, append (token, weight) to expert lists
// ---------------------------------------------------------------------------
__global__ void router_kernel(const float* __restrict__ x,
                              const float* __restrict__ gw,
                              float* __restrict__ out) {
    int t = blockIdx.x;
    __shared__ float xs[HDIM];
    __shared__ float logits[ENUM];
    __shared__ float probs[ENUM];

    const float* xr = x + (size_t)t * HDIM;
    for (int i = threadIdx.x; i < HDIM; i += blockDim.x) xs[i] = xr[i];
    __syncthreads();

    int e = threadIdx.x >> 2;
    int part = threadIdx.x & 3;
    float s = 0.f;
    int k0 = part * (HDIM / 4);
    for (int k = k0; k < k0 + HDIM / 4; k++)
        s += xs[k] * gw[(size_t)k * ENUM + e];
    s += __shfl_down_sync(0xffffffffu, s, 2);
    s += __shfl_down_sync(0xffffffffu, s, 1);
    if (part == 0) logits[e] = s;
    __syncthreads();

    if (threadIdx.x < ENUM)
        out[(size_t)TTOK * HDIM + (size_t)t * ENUM + threadIdx.x] = logits[threadIdx.x];

    if (threadIdx.x == 0) {
        float m = -1e30f;
        for (int i = 0; i < ENUM; i++) m = fmaxf(m, logits[i]);
        float sum = 0.f;
        for (int i = 0; i < ENUM; i++) { probs[i] = expf(logits[i] - m); sum += probs[i]; }
        float inv = 1.f / sum;
        for (int k = 0; k < KTOP; k++) {
            int best = 0; float bv = -1.f;
            for (int i = 0; i < ENUM; i++)
                if (probs[i] > bv) { bv = probs[i]; best = i; }
            probs[best] = -2.f;
            int pos = atomicAdd(&g_cnt[best], 1);
            g_tok[best * TTOK + pos] = t;
            g_wt[best * TTOK + pos]  = bv * inv;
        }
    }
}

// ---------------------------------------------------------------------------
// K2: exclusive prefix sum over expert counts
// ---------------------------------------------------------------------------
__global__ void scan_kernel() {
    if (threadIdx.x == 0) {
        int acc = 0;
        for (int e = 0; e < ENUM; e++) { g_off[e] = acc; acc += g_cnt[e]; }
    }
}

// ---------------------------------------------------------------------------
// K3: gateup via bf16x3 mma. 512 threads, 16 warps, warptile m16n32 per mat.
//     CTA tile: M=128, N=64 (both gate & up), BK=16.
// ---------------------------------------------------------------------------
#define GU_ITERS (HDIM / 16)

__global__ __launch_bounds__(512, 1)
void gateup_mma(const float* __restrict__ x,
                const float* __restrict__ wgp,
                const float* __restrict__ wup) {
    int e = blockIdx.z;
    int cnt = g_cnt[e];
    int mblk = blockIdx.y * 128;
    if (mblk >= cnt) return;
    int nblk = blockIdx.x * 64;

    __shared__ unsigned short Ah[2][128][24], Al[2][128][24];
    __shared__ unsigned short Bh[2][2][16][72], Bl[2][2][16][72]; // [stage][mat][k][n]

    const int tid = threadIdx.x;
    const int lane = tid & 31, warp = tid >> 5;
    const int wm = warp >> 1, wn = warp & 1;   // wm: 16-row block, wn: 32-col block

    // A tile load: 128m x 16k, one float4 per thread
    const int am = tid >> 2;
    const int ak = (tid & 3) * 4;
    int mrow = min(mblk + am, cnt - 1);
    const float* arow = x + (size_t)g_tok[e * TTOK + mrow] * HDIM + ak;

    // B tile load: 2 mats x 16k x 64n, one float4 per thread
    const int bmat = tid >> 8;
    const int brem = tid & 255;
    const int bk = brem >> 4;
    const int bn = (brem & 15) * 4;
    const float* Wsel = (bmat ? wup : wgp) + (size_t)e * HDIM * IDIM;
    const float* brow = Wsel + (size_t)bk * IDIM + nblk + bn;

    float4 pa = *(const float4*)arow;
    float4 pb = *(const float4*)brow;

    float cg[4][4] = {}, cu[4][4] = {};

    int s = 0;
    {
        uint32_t h0, l0, h1, l1;
        splitf(pa.x, pa.y, h0, l0); splitf(pa.z, pa.w, h1, l1);
        *(uint2*)&Ah[0][am][ak] = make_uint2(h0, h1);
        *(uint2*)&Al[0][am][ak] = make_uint2(l0, l1);
        splitf(pb.x, pb.y, h0, l0); splitf(pb.z, pb.w, h1, l1);
        *(uint2*)&Bh[0][bmat][bk][bn] = make_uint2(h0, h1);
        *(uint2*)&Bl[0][bmat][bk][bn] = make_uint2(l0, l1);
    }
    __syncthreads();

    for (int it = 0; it < GU_ITERS; ++it) {
        if (it + 1 < GU_ITERS) {
            pa = *(const float4*)(arow + (it + 1) * 16);
            pb = *(const float4*)(brow + (size_t)(it + 1) * 16 * IDIM);
        }

        uint32_t aH[4], aL[4];
        {
            uint32_t ad = cvsm(&Ah[s][wm * 16 + (lane & 15)][(lane >> 4) * 8]);
            ldsm4(aH[0], aH[1], aH[2], aH[3], ad);
            uint32_t ad2 = cvsm(&Al[s][wm * 16 + (lane & 15)][(lane >> 4) * 8]);
            ldsm4(aL[0], aL[1], aL[2], aL[3], ad2);
        }
        uint32_t bgH[4][2], bgL[4][2], buH[4][2], buL[4][2];
#pragma unroll
        for (int p = 0; p < 2; p++) {
            int col = wn * 32 + p * 16 + (lane >> 4) * 8;
            int row = lane & 15;
            uint32_t d0 = cvsm(&Bh[s][0][row][col]);
            ldsm4t(bgH[2 * p][0], bgH[2 * p][1], bgH[2 * p + 1][0], bgH[2 * p + 1][1], d0);
            uint32_t d1 = cvsm(&Bl[s][0][row][col]);
            ldsm4t(bgL[2 * p][0], bgL[2 * p][1], bgL[2 * p + 1][0], bgL[2 * p + 1][1], d1);
            uint32_t d2 = cvsm(&Bh[s][1][row][col]);
            ldsm4t(buH[2 * p][0], buH[2 * p][1], buH[2 * p + 1][0], buH[2 * p + 1][1], d2);
            uint32_t d3 = cvsm(&Bl[s][1][row][col]);
            ldsm4t(buL[2 * p][0], buL[2 * p][1], buL[2 * p + 1][0], buL[2 * p + 1][1], d3);
        }
#pragma unroll
        for (int nf = 0; nf < 4; nf++) {
            mma16816(cg[nf], aH, bgH[nf]);
            mma16816(cg[nf], aH, bgL[nf]);
            mma16816(cg[nf], aL, bgH[nf]);
            mma16816(cu[nf], aH, buH[nf]);
            mma16816(cu[nf], aH, buL[nf]);
            mma16816(cu[nf], aL, buH[nf]);
        }

        if (it + 1 < GU_ITERS) {
            uint32_t h0, l0, h1, l1;
            splitf(pa.x, pa.y, h0, l0); splitf(pa.z, pa.w, h1, l1);
            *(uint2*)&Ah[s ^ 1][am][ak] = make_uint2(h0, h1);
            *(uint2*)&Al[s ^ 1][am][ak] = make_uint2(l0, l1);
            splitf(pb.x, pb.y, h0, l0); splitf(pb.z, pb.w, h1, l1);
            *(uint2*)&Bh[s ^ 1][bmat][bk][bn] = make_uint2(h0, h1);
            *(uint2*)&Bl[s ^ 1][bmat][bk][bn] = make_uint2(l0, l1);
        }
        __syncthreads();
        s ^= 1;
    }

    // epilogue: SiLU(gate)*up -> g_h
    int goff = g_off[e];
    int gr = lane >> 2, cc = (lane & 3) * 2;
#pragma unroll
    for (int nf = 0; nf < 4; nf++) {
        int nab = nblk + wn * 32 + nf * 8 + cc;
#pragma unroll
        for (int half = 0; half < 2; half++) {
            int m = mblk + wm * 16 + gr + half * 8;
            if (m < cnt) {
                float g0 = cg[nf][half * 2], g1 = cg[nf][half * 2 + 1];
                float u0 = cu[nf][half * 2], u1 = cu[nf][half * 2 + 1];
                float h0 = g0 / (1.f + expf(-g0)) * u0;
                float h1 = g1 / (1.f + expf(-g1)) * u1;
                *(float2*)&g_h[(size_t)(goff + m) * IDIM + nab] = make_float2(h0, h1);
            }
        }
    }
}

// ---------------------------------------------------------------------------
// K4: down via bf16x3 mma + weighted atomic scatter.
//     512 threads, 16 warps, warptile m32n32. CTA tile: 128x128, BK=16.
// ---------------------------------------------------------------------------
#define DN_ITERS (IDIM / 16)

__global__ __launch_bounds__(512, 1)
void down_mma(const float* __restrict__ wdp,
              float* __restrict__ out) {
    int e = blockIdx.z;
    int cnt = g_cnt[e];
    int mblk = blockIdx.y * 128;
    if (mblk >= cnt) return;
    int nblk = blockIdx.x * 128;

    __shared__ unsigned short Ah[2][128][24], Al[2][128][24];
    __shared__ unsigned short Bh[2][16][136], Bl[2][16][136];  // [stage][k][n]

    const int tid = threadIdx.x;
    const int lane = tid & 31, warp = tid >> 5;
    const int wm = warp >> 2, wn = warp & 3;   // wm: 32-row block, wn: 32-col block

    const int am = tid >> 2;
    const int ak = (tid & 3) * 4;
    int goff = g_off[e];
    int mrow = min(mblk + am, cnt - 1);
    const float* arow = g_h + (size_t)(goff + mrow) * IDIM + ak;

    const int bk = tid >> 5;
    const int bn = (tid & 31) * 4;
    const float* brow = wdp + (size_t)e * IDIM * HDIM + (size_t)bk * HDIM + nblk + bn;

    float4 pa = *(const float4*)arow;
    float4 pb = *(const float4*)brow;

    float cacc[2][4][4] = {};

    int s = 0;
    {
        uint32_t h0, l0, h1, l1;
        splitf(pa.x, pa.y, h0, l0); splitf(pa.z, pa.w, h1, l1);
        *(uint2*)&Ah[0][am][ak] = make_uint2(h0, h1);
        *(uint2*)&Al[0][am][ak] = make_uint2(l0, l1);
        splitf(pb.x, pb.y, h0, l0); splitf(pb.z, pb.w, h1, l1);
        *(uint2*)&Bh[0][bk][bn] = make_uint2(h0, h1);
        *(uint2*)&Bl[0][bk][bn] = make_uint2(l0, l1);
    }
    __syncthreads();

    for (int it = 0; it < DN_ITERS; ++it) {
        if (it + 1 < DN_ITERS) {
            pa = *(const float4*)(arow + (it + 1) * 16);
            pb = *(const float4*)(brow + (size_t)(it + 1) * 16 * HDIM);
        }

        uint32_t aH[2][4], aL[2][4];
#pragma unroll
        for (int mf = 0; mf < 2; mf++) {
            uint32_t ad = cvsm(&Ah[s][wm * 32 + mf * 16 + (lane & 15)][(lane >> 4) * 8]);
            ldsm4(aH[mf][0], aH[mf][1], aH[mf][2], aH[mf][3], ad);
            uint32_t ad2 = cvsm(&Al[s][wm * 32 + mf * 16 + (lane & 15)][(lane >> 4) * 8]);
            ldsm4(aL[mf][0], aL[mf][1], aL[mf][2], aL[mf][3], ad2);
        }
        uint32_t bH[4][2], bL[4][2];
#pragma unroll
        for (int p = 0; p < 2; p++) {
            int col = wn * 32 + p * 16 + (lane >> 4) * 8;
            int row = lane & 15;
            uint32_t d0 = cvsm(&Bh[s][row][col]);
            ldsm4t(bH[2 * p][0], bH[2 * p][1], bH[2 * p + 1][0], bH[2 * p + 1][1], d0);
            uint32_t d1 = cvsm(&Bl[s][row][col]);
            ldsm4t(bL[2 * p][0], bL[2 * p][1], bL[2 * p + 1][0], bL[2 * p + 1][1], d1);
        }
#pragma unroll
        for (int mf = 0; mf < 2; mf++)
#pragma unroll
            for (int nf = 0; nf < 4; nf++) {
                mma16816(cacc[mf][nf], aH[mf], bH[nf]);
                mma16816(cacc[mf][nf], aH[mf], bL[nf]);
                mma16816(cacc[mf][nf], aL[mf], bH[nf]);
            }

        if (it + 1 < DN_ITERS) {
            uint32_t h0, l0, h1, l1;
            splitf(pa.x, pa.y, h0, l0); splitf(pa.z, pa.w, h1, l1);
            *(uint2*)&Ah[s ^ 1][am][ak] = make_uint2(h0, h1);
            *(uint2*)&Al[s ^ 1][am][ak] = make_uint2(l0, l1);
            splitf(pb.x, pb.y, h0, l0); splitf(pb.z, pb.w, h1, l1);
            *(uint2*)&Bh[s ^ 1][bk][bn] = make_uint2(h0, h1);
            *(uint2*)&Bl[s ^ 1][bk][bn] = make_uint2(l0, l1);
        }
        __syncthreads();
        s ^= 1;
    }

    // epilogue: weighted atomic scatter into out
    int gr = lane >> 2, cc = (lane & 3) * 2;
#pragma unroll
    for (int mf = 0; mf < 2; mf++) {
#pragma unroll
        for (int half = 0; half < 2; half++) {
            int m = mblk + wm * 32 + mf * 16 + gr + half * 8;
            if (m < cnt) {
                int tok = g_tok[e * TTOK + m];
                float w = g_wt[e * TTOK + m];
                float* orow = out + (size_t)tok * HDIM;
#pragma unroll
                for (int nf = 0; nf < 4; nf++) {
                    int nab = nblk + wn * 32 + nf * 8 + cc;
                    atomicAdd(&orow[nab],     w * cacc[mf][nf][half * 2]);
                    atomicAdd(&orow[nab + 1], w * cacc[mf][nf][half * 2 + 1]);
                }
            }
        }
    }
}

// ---------------------------------------------------------------------------
extern "C" void kernel_launch(void* const* d_in, const int* in_sizes, int n_in,
                              void* d_out, int out_size) {
    const float* x  = (const float*)d_in[0];   // hidden_states [2,1024,2048]
    const float* gw = (const float*)d_in[1];   // gate_w [2048,64]
    const float* wg = (const float*)d_in[2];   // w_gate_proj [64,2048,1024]
    const float* wu = (const float*)d_in[3];   // w_up_proj   [64,2048,1024]
    const float* wd = (const float*)d_in[4];   // w_down_proj [64,1024,2048]
    float* out = (float*)d_out;                // [final | router_logits]

    zero_kernel<<<1024, 256>>>(out);
    router_kernel<<<TTOK, 256>>>(x, gw, out);
    scan_kernel<<<1, 32>>>();
    gateup_mma<<<dim3(16, 16, 64), 512>>>(x, wg, wu);
    down_mma<<<dim3(16, 16, 64), 512>>>(wd, out);
}